// round 6
// baseline (speedup 1.0000x reference)
#include <cuda_runtime.h>
#include <math.h>

// ---------------------------------------------------------------------------
// PathGuidedAggregator: S=8192 x P=16 x K=16, D=128, H=64
// Round 4: Phase-B retile dq8/j16(jt=4)/p4(pt=4): W1 requested 4x/element
// (was 8x), agg 16x -> B-read 3072 -> 2048 cyc/node. Path-consecutive pt=4
// uses conflict-free scalar broadcast loads on the stride-132 sAgg layout.
// Phase A chunked (2 int4 live) to hold regs <= 42 @ 3 blocks/SM.
// ---------------------------------------------------------------------------

#define DD 128
#define PP 16
#define KK 16
#define HH 64
#define AGG_STRIDE 132           // floats per sAgg row
#define PART_PSTRIDE 33          // ull per path row in sPart
#define PART_DQ (16 * PART_PSTRIDE)  // 528 ull per d-sixteenth bank

__device__ int g_mask_mode; // 0 = uint8, 1 = int32, 2 = float32

__global__ void detect_mask_kernel(const unsigned int* __restrict__ w) {
    __shared__ int f_gt1, f_one;
    if (threadIdx.x == 0) { f_gt1 = 0; f_one = 0; }
    __syncthreads();
    unsigned v = w[threadIdx.x];
    if (v == 0x3F800000u)      atomicOr(&f_one, 1);
    else if (v > 1u)           atomicOr(&f_gt1, 1);
    __syncthreads();
    if (threadIdx.x == 0)
        g_mask_mode = f_gt1 ? 0 : (f_one ? 2 : 1);
}

// ---- packed f32x2 helpers (sm_100+) ---------------------------------------
__device__ __forceinline__ unsigned long long pack2(float x, float y) {
    unsigned long long r;
    asm("mov.b64 %0, {%1, %2};" : "=l"(r) : "f"(x), "f"(y));
    return r;
}
__device__ __forceinline__ float2 unpack2(unsigned long long v) {
    float2 r;
    asm("mov.b64 {%0, %1}, %2;" : "=f"(r.x), "=f"(r.y) : "l"(v));
    return r;
}
__device__ __forceinline__ void fma2(unsigned long long& acc,
                                     unsigned long long a,
                                     unsigned long long b) {
    asm("fma.rn.f32x2 %0, %1, %2, %0;" : "+l"(acc) : "l"(a), "l"(b));
}

// Dynamic SMEM layout (float index):
//   sW1   [0     .. 8192)    32 KB   W1[d][j] row-major
//   sAgg  [8192  .. 10304)   16 x 132 floats
//   sPart [10304 .. 18752)   8 dq x 528 ull (33.8 KB)
//   sWgt  [18752 .. 18768)
//   sVal  [18768 .. 18784)  (int)
static const int SMEM_FLOATS = 18784;

__global__ void __launch_bounds__(512, 3)
pga_kernel(const float* __restrict__ E, const float* __restrict__ W1,
           const float* __restrict__ b1, const float* __restrict__ W2,
           const float* __restrict__ b2, const int* __restrict__ sids,
           const int* __restrict__ eids, const void* __restrict__ maskp,
           float* __restrict__ out, int S) {
    extern __shared__ float smem[];
    float* sW1  = smem;
    float* sAgg = smem + 8192;
    unsigned long long* sPart = (unsigned long long*)(smem + 10304);
    float* sWgt = smem + 18752;
    int*   sVal = (int*)(smem + 18768);

    const int t = threadIdx.x;
    const int lane = t & 31;
    const int warp = t >> 5;

    // W1 -> smem (vectorized)
    {
        const float4* w4 = (const float4*)W1;
        #pragma unroll
        for (int i = t; i < DD * HH / 4; i += 512)
            ((float4*)sW1)[i] = __ldg(w4 + i);
    }
    // Phase C per-thread constants (indexed by lane only)
    const float rb1x = __ldg(b1 + 2 * lane);
    const float rb1y = __ldg(b1 + 2 * lane + 1);
    const float rw2x = __ldg(W2 + 2 * lane);
    const float rw2y = __ldg(W2 + 2 * lane + 1);
    const float bias2 = __ldg(b2);
    const int mode = g_mask_mode;
    __syncthreads();

    // Phase B thread decomposition: t = dq*64 + jgrp*4 + pgrp
    const int dq   = t >> 6;        // 0..7  -> d in [dq*16, dq*16+16)
    const int jgrp = (t >> 2) & 15; // j = jgrp*4 .. +3 (pairs 2*jgrp, 2*jgrp+1)
    const int pgrp = t & 3;         // paths pgrp*4 .. +3

    for (int s = blockIdx.x; s < S; s += gridDim.x) {
        // ---------------- Phase A: gather (warp p <-> path p) --------------
        {
            const int p = warp;
            const int base = (s * PP + p) * KK;
            const int4* ip = (const int4*)(eids + base);

            unsigned mb = 0;
            if (mode == 0) {
                uint4 mv = __ldg((const uint4*)((const unsigned char*)maskp + base));
                unsigned wds[4] = {mv.x, mv.y, mv.z, mv.w};
                #pragma unroll
                for (int q = 0; q < 4; q++)
                    #pragma unroll
                    for (int b = 0; b < 4; b++)
                        mb |= (((wds[q] >> (8 * b)) & 0xFFu) ? 1u : 0u) << (q * 4 + b);
            } else if (mode == 1) {
                const int4* m4 = (const int4*)((const int*)maskp + base);
                #pragma unroll
                for (int q = 0; q < 4; q++) {
                    int4 mv = __ldg(m4 + q);
                    mb |= (mv.x ? 1u : 0u) << (q * 4 + 0);
                    mb |= (mv.y ? 1u : 0u) << (q * 4 + 1);
                    mb |= (mv.z ? 1u : 0u) << (q * 4 + 2);
                    mb |= (mv.w ? 1u : 0u) << (q * 4 + 3);
                }
            } else {
                const float4* m4 = (const float4*)((const float*)maskp + base);
                #pragma unroll
                for (int q = 0; q < 4; q++) {
                    float4 mv = __ldg(m4 + q);
                    mb |= (mv.x != 0.f ? 1u : 0u) << (q * 4 + 0);
                    mb |= (mv.y != 0.f ? 1u : 0u) << (q * 4 + 1);
                    mb |= (mv.z != 0.f ? 1u : 0u) << (q * 4 + 2);
                    mb |= (mv.w != 0.f ? 1u : 0u) << (q * 4 + 3);
                }
            }
            const int cnt = __popc(mb);

            const float4* E4 = (const float4*)E;
            float4 acc = make_float4(0.f, 0.f, 0.f, 0.f);
            // two chunks of 8 endpoints: keeps only 2 int4 of ids live
            #pragma unroll
            for (int h = 0; h < 2; h++) {
                int4 ia = __ldg(ip + 2 * h);
                int4 ib = __ldg(ip + 2 * h + 1);
                const int ids8[8] = {ia.x, ia.y, ia.z, ia.w, ib.x, ib.y, ib.z, ib.w};
                #pragma unroll
                for (int k = 0; k < 8; k++) {
                    if (mb & (1u << (8 * h + k))) {
                        float4 v = __ldg(E4 + ids8[k] * (DD / 4) + lane);
                        acc.x += v.x; acc.y += v.y; acc.z += v.z; acc.w += v.w;
                    }
                }
            }
            const float inv = 1.f / (float)(cnt > 0 ? cnt : 1);
            float4 a = make_float4(acc.x * inv, acc.y * inv, acc.z * inv, acc.w * inv);
            ((float4*)(sAgg + p * AGG_STRIDE))[lane] = a;
            if (lane == 0) sVal[p] = (cnt > 0);
        }
        __syncthreads();

        // -------- Phase B: tiled split-K GEMM h[p][j] partials --------------
        // thread: dq (16 d's), jgrp (4 j's), pgrp (4 consecutive paths)
        {
            const float* wp = sW1 + (dq * 16) * HH + jgrp * 4;
            const float* ap = sAgg + (pgrp * 4) * AGG_STRIDE + dq * 16;
            unsigned long long h0 = 0ull, h1 = 0ull, h2 = 0ull, h3 = 0ull;
            unsigned long long h4 = 0ull, h5 = 0ull, h6 = 0ull, h7 = 0ull;
            #pragma unroll
            for (int dd = 0; dd < 16; dd++) {
                ulonglong2 w = *(const ulonglong2*)(wp + dd * HH);
                float a0 = ap[dd];
                float a1 = ap[AGG_STRIDE + dd];
                float a2 = ap[2 * AGG_STRIDE + dd];
                float a3 = ap[3 * AGG_STRIDE + dd];
                unsigned long long aa;
                aa = pack2(a0, a0); fma2(h0, aa, w.x); fma2(h1, aa, w.y);
                aa = pack2(a1, a1); fma2(h2, aa, w.x); fma2(h3, aa, w.y);
                aa = pack2(a2, a2); fma2(h4, aa, w.x); fma2(h5, aa, w.y);
                aa = pack2(a3, a3); fma2(h6, aa, w.x); fma2(h7, aa, w.y);
            }
            unsigned long long* pd = sPart + dq * PART_DQ;
            const int pb = pgrp * 4;
            pd[(pb + 0) * PART_PSTRIDE + jgrp * 2 + 0] = h0;
            pd[(pb + 0) * PART_PSTRIDE + jgrp * 2 + 1] = h1;
            pd[(pb + 1) * PART_PSTRIDE + jgrp * 2 + 0] = h2;
            pd[(pb + 1) * PART_PSTRIDE + jgrp * 2 + 1] = h3;
            pd[(pb + 2) * PART_PSTRIDE + jgrp * 2 + 0] = h4;
            pd[(pb + 2) * PART_PSTRIDE + jgrp * 2 + 1] = h5;
            pd[(pb + 3) * PART_PSTRIDE + jgrp * 2 + 0] = h6;
            pd[(pb + 3) * PART_PSTRIDE + jgrp * 2 + 1] = h7;
        }
        __syncthreads();

        // ------- Phase C: reduce split-K, bias+relu, dot W2, sigmoid -------
        // warp == path p; lane == j-pair index (j = 2*lane, 2*lane+1)
        {
            const int p = warp;
            float hx = 0.f, hy = 0.f;
            #pragma unroll
            for (int dqq = 0; dqq < 8; dqq++) {
                float2 v = unpack2(sPart[dqq * PART_DQ + p * PART_PSTRIDE + lane]);
                hx += v.x; hy += v.y;
            }
            float h0 = fmaxf(hx + rb1x, 0.f);
            float h1 = fmaxf(hy + rb1y, 0.f);
            float hw = h0 * rw2x + h1 * rw2y;
            #pragma unroll
            for (int o = 16; o; o >>= 1) hw += __shfl_xor_sync(0xffffffffu, hw, o);
            if (lane == 0) {
                float x = hw + bias2;
                float w = 1.f / (1.f + expf(-x));
                sWgt[p] = sVal[p] ? w : 0.f;
            }
        }
        __syncthreads();

        // -------- Phase D: weighted mean over valid paths + scatter --------
        if (t < DD) {
            float o = 0.f;
            int nv = 0;
            #pragma unroll
            for (int p = 0; p < PP; p++) {
                o += sWgt[p] * sAgg[p * AGG_STRIDE + t];
                nv += sVal[p];
            }
            out[__ldg(sids + s) * DD + t] = o / (float)(nv > 0 ? nv : 1);
        }
        __syncthreads();
    }
}

extern "C" void kernel_launch(void* const* d_in, const int* in_sizes, int n_in,
                              void* d_out, int out_size) {
    const float* E   = (const float*)d_in[0];
    const float* W1  = (const float*)d_in[1];
    const float* b1  = (const float*)d_in[2];
    const float* W2  = (const float*)d_in[3];
    const float* b2  = (const float*)d_in[4];
    const int*   sid = (const int*)d_in[5];
    const int*   eid = (const int*)d_in[6];
    const void*  msk = d_in[7];
    float* out = (float*)d_out;

    const int S = in_sizes[5];

    cudaMemsetAsync(d_out, 0, (size_t)out_size * sizeof(float), 0);
    detect_mask_kernel<<<1, 1024>>>((const unsigned int*)msk);

    static const int SMEM_BYTES = SMEM_FLOATS * 4; // 75136 B
    cudaFuncSetAttribute(pga_kernel, cudaFuncAttributeMaxDynamicSharedMemorySize,
                         SMEM_BYTES);

    // 152 SMs x 3 blocks/SM = 456 persistent blocks.
    int grid = 456;
    if (grid > S) grid = S;
    pga_kernel<<<grid, 512, SMEM_BYTES>>>(E, W1, b1, W2, b2, sid, eid, msk, out, S);
}